// round 3
// baseline (speedup 1.0000x reference)
#include <cuda_runtime.h>
#include <math.h>

#define BB   2
#define SS   2048
#define DDIM 1024
#define HH   16
#define HDIM 64
#define MM   (BB*SS)          // 4096 rows
#define NKT  32               // key tiles per (b,h)
#define CHUNK_TILES 16        // 1024 keys / 64

// Scratch (allocation-free rule: __device__ globals)
__device__ float g_q[BB*HH*SS*HDIM];
__device__ float g_k[BB*HH*SS*HDIM];
__device__ float g_v[BB*HH*SS*HDIM];
__device__ float g_att[MM*DDIM];

// ---------------------------------------------------------------------------
// QKV projection GEMM: C = X[4096,1024] @ W[1024,1024]
// blockIdx.z: 0=Q(+rope) 1=K(+rope) 2=V. Output layout [B,H,S,HD].
// Tile 64x64, Kstep 16, 256 threads, 4x4 micro-tiles.
// ---------------------------------------------------------------------------
__global__ __launch_bounds__(256) void qkv_gemm_kernel(
    const float* __restrict__ X,
    const float* __restrict__ Wq,
    const float* __restrict__ Wk,
    const float* __restrict__ Wv,
    const float* __restrict__ freqs)
{
    __shared__ float As[16][68];   // As[k][m] (transposed)
    __shared__ float Bs[16][68];   // Bs[k][n]
    const int mode = blockIdx.z;
    const float* __restrict__ W = (mode == 0) ? Wq : (mode == 1) ? Wk : Wv;
    const int m0 = blockIdx.y * 64;
    const int n0 = blockIdx.x * 64;
    const int t  = threadIdx.x;
    const int tx = t & 15, ty = t >> 4;
    const int ar = t >> 2, ak = (t & 3) * 4;   // A: row 0..63, kk 0,4,8,12
    const int bk = t >> 4, bn = (t & 15) * 4;  // B: kk 0..15, n 0..60

    float acc[4][4] = {};

    for (int k0 = 0; k0 < DDIM; k0 += 16) {
        float4 av = *(const float4*)&X[(m0 + ar) * DDIM + k0 + ak];
        float4 bv = *(const float4*)&W[(k0 + bk) * DDIM + n0 + bn];
        __syncthreads();
        As[ak+0][ar] = av.x; As[ak+1][ar] = av.y;
        As[ak+2][ar] = av.z; As[ak+3][ar] = av.w;
        *(float4*)&Bs[bk][bn] = bv;
        __syncthreads();
        #pragma unroll
        for (int kk = 0; kk < 16; kk++) {
            float4 a = *(const float4*)&As[kk][ty*4];
            float4 b = *(const float4*)&Bs[kk][tx*4];
            float aa[4] = {a.x, a.y, a.z, a.w};
            float bb[4] = {b.x, b.y, b.z, b.w};
            #pragma unroll
            for (int i = 0; i < 4; i++)
                #pragma unroll
                for (int j = 0; j < 4; j++)
                    acc[i][j] += aa[i] * bb[j];
        }
    }

    const int hh = n0 >> 6;       // head (64-wide N tile == one head)
    const int nl = tx * 4;        // local dim within head, even
    if (mode == 2) {
        float* __restrict__ dst = g_v;
        #pragma unroll
        for (int i = 0; i < 4; i++) {
            int m = m0 + ty*4 + i;
            int b = m >> 11, s = m & 2047;
            float4 r = make_float4(acc[i][0], acc[i][1], acc[i][2], acc[i][3]);
            *(float4*)&dst[((b*HH + hh)*SS + s)*HDIM + nl] = r;
        }
    } else {
        float* __restrict__ dst = (mode == 0) ? g_q : g_k;
        #pragma unroll
        for (int i = 0; i < 4; i++) {
            int m = m0 + ty*4 + i;
            int b = m >> 11, s = m & 2047;
            const float* F = freqs + s*HDIM + nl;  // [s][nl/2][0] = cos
            float c0 = F[0], s0 = F[1], c1 = F[2], s1 = F[3];
            float a0 = acc[i][0], b0 = acc[i][1];
            float a1 = acc[i][2], b1 = acc[i][3];
            float4 r;
            r.x = a0*c0 - b0*s0;
            r.y = a0*s0 + b0*c0;
            r.z = a1*c1 - b1*s1;
            r.w = a1*s1 + b1*c1;
            *(float4*)&dst[((b*HH + hh)*SS + s)*HDIM + nl] = r;
        }
    }
}

// ---------------------------------------------------------------------------
// Attention: per block = (q_tile 64, h, b). Online softmax with per-1024-key
// chunk normalization + reset (replicates reference's chunked softmax).
// Writes output directly in [B,S,D] layout into g_att.
// ---------------------------------------------------------------------------
#define ATT_SMEM (4 * 64 * 68 * 4)

__global__ __launch_bounds__(256) void attn_kernel()
{
    extern __shared__ float sm[];
    float* Qs = sm;               // Qs[d][q]  64x68
    float* Ks = sm + 64*68;       // Ks[d][k]
    float* Vs = sm + 2*64*68;     // Vs[k][d]
    float* Ps = sm + 3*64*68;     // Ps[q][k]

    const int qt = blockIdx.x;
    const int h  = blockIdx.y;
    const int b  = blockIdx.z;
    const int t  = threadIdx.x;
    const int tx = t & 15, ty = t >> 4;
    const int tx4 = tx * 4, ty4 = ty * 4;

    const float* __restrict__ Qg = g_q + (((size_t)b*HH + h)*SS + qt*64) * HDIM;
    const float* __restrict__ Kg = g_k + (((size_t)b*HH + h)*SS) * HDIM;
    const float* __restrict__ Vg = g_v + (((size_t)b*HH + h)*SS) * HDIM;

    // Load Q tile transposed: Qs[d][q]
    {
        const int dd = (t & 15) * 4;
        #pragma unroll
        for (int r = 0; r < 4; r++) {
            int row = (t >> 4) + r * 16;
            float4 v = *(const float4*)&Qg[row*HDIM + dd];
            Qs[(dd+0)*68 + row] = v.x; Qs[(dd+1)*68 + row] = v.y;
            Qs[(dd+2)*68 + row] = v.z; Qs[(dd+3)*68 + row] = v.w;
        }
    }

    float m[4], l[4], o[4][4] = {}, oT[4][4] = {};
    #pragma unroll
    for (int i = 0; i < 4; i++) { m[i] = -INFINITY; l[i] = 0.f; }

    for (int kt = 0; kt < NKT; kt++) {
        __syncthreads();   // protect previous iteration's Vs/Ps reads
        // Load K (transposed) and V tiles
        {
            const int dd = (t & 15) * 4;
            #pragma unroll
            for (int r = 0; r < 4; r++) {
                int row = (t >> 4) + r * 16;
                float4 kv = *(const float4*)&Kg[(kt*64 + row)*HDIM + dd];
                Ks[(dd+0)*68 + row] = kv.x; Ks[(dd+1)*68 + row] = kv.y;
                Ks[(dd+2)*68 + row] = kv.z; Ks[(dd+3)*68 + row] = kv.w;
                float4 vv = *(const float4*)&Vg[(kt*64 + row)*HDIM + dd];
                *(float4*)&Vs[row*68 + dd] = vv;
            }
        }
        __syncthreads();

        // S = Q @ K^T  (64x64x64)
        float s[4][4] = {};
        #pragma unroll 8
        for (int d = 0; d < 64; d++) {
            float4 a = *(const float4*)&Qs[d*68 + ty4];
            float4 kk = *(const float4*)&Ks[d*68 + tx4];
            float aa[4] = {a.x, a.y, a.z, a.w};
            float bb[4] = {kk.x, kk.y, kk.z, kk.w};
            #pragma unroll
            for (int i = 0; i < 4; i++)
                #pragma unroll
                for (int j = 0; j < 4; j++)
                    s[i][j] += aa[i] * bb[j];
        }

        // Online softmax (per row), reduce across 16 tx lanes via shfl
        #pragma unroll
        for (int i = 0; i < 4; i++) {
            float mt = -INFINITY;
            #pragma unroll
            for (int j = 0; j < 4; j++) {
                s[i][j] *= 0.125f;                 // HD^-0.5
                mt = fmaxf(mt, s[i][j]);
            }
            #pragma unroll
            for (int ofs = 8; ofs >= 1; ofs >>= 1)
                mt = fmaxf(mt, __shfl_xor_sync(0xffffffffu, mt, ofs));
            float mn = fmaxf(m[i], mt);
            float alpha = __expf(m[i] - mn);
            float rs = 0.f;
            #pragma unroll
            for (int j = 0; j < 4; j++) {
                float p = __expf(s[i][j] - mn);
                s[i][j] = p;
                rs += p;
            }
            #pragma unroll
            for (int ofs = 8; ofs >= 1; ofs >>= 1)
                rs += __shfl_xor_sync(0xffffffffu, rs, ofs);
            l[i] = l[i] * alpha + rs;
            m[i] = mn;
            #pragma unroll
            for (int j = 0; j < 4; j++) o[i][j] *= alpha;
        }

        // Stage P to shared: Ps[q][k] (float4, conflict-free)
        #pragma unroll
        for (int i = 0; i < 4; i++)
            *(float4*)&Ps[(ty4+i)*68 + tx4] =
                make_float4(s[i][0], s[i][1], s[i][2], s[i][3]);
        __syncthreads();

        // O += P @ V  (64x64x64)
        #pragma unroll 4
        for (int k4 = 0; k4 < 64; k4 += 4) {
            float4 p0 = *(const float4*)&Ps[(ty4+0)*68 + k4];
            float4 p1 = *(const float4*)&Ps[(ty4+1)*68 + k4];
            float4 p2 = *(const float4*)&Ps[(ty4+2)*68 + k4];
            float4 p3 = *(const float4*)&Ps[(ty4+3)*68 + k4];
            float4 v0 = *(const float4*)&Vs[(k4+0)*68 + tx4];
            float4 v1 = *(const float4*)&Vs[(k4+1)*68 + tx4];
            float4 v2 = *(const float4*)&Vs[(k4+2)*68 + tx4];
            float4 v3 = *(const float4*)&Vs[(k4+3)*68 + tx4];
            float pa[4][4] = {{p0.x,p0.y,p0.z,p0.w},{p1.x,p1.y,p1.z,p1.w},
                              {p2.x,p2.y,p2.z,p2.w},{p3.x,p3.y,p3.z,p3.w}};
            float va[4][4] = {{v0.x,v0.y,v0.z,v0.w},{v1.x,v1.y,v1.z,v1.w},
                              {v2.x,v2.y,v2.z,v2.w},{v3.x,v3.y,v3.z,v3.w}};
            #pragma unroll
            for (int u = 0; u < 4; u++)
                #pragma unroll
                for (int i = 0; i < 4; i++)
                    #pragma unroll
                    for (int j = 0; j < 4; j++)
                        o[i][j] += pa[i][u] * va[u][j];
        }

        // Chunk boundary: normalize by this chunk's softmax sum, accumulate, reset
        if ((kt & (CHUNK_TILES - 1)) == (CHUNK_TILES - 1)) {
            #pragma unroll
            for (int i = 0; i < 4; i++) {
                float inv = 1.f / l[i];
                #pragma unroll
                for (int j = 0; j < 4; j++) {
                    oT[i][j] += o[i][j] * inv;
                    o[i][j] = 0.f;
                }
                m[i] = -INFINITY;
                l[i] = 0.f;
            }
        }
    }

    // Store to [B,S,D]: row (b, q), cols h*64 + d
    #pragma unroll
    for (int i = 0; i < 4; i++) {
        int q = qt*64 + ty4 + i;
        float4 r = make_float4(oT[i][0], oT[i][1], oT[i][2], oT[i][3]);
        *(float4*)&g_att[((size_t)(b*SS + q))*DDIM + h*HDIM + tx4] = r;
    }
}

// ---------------------------------------------------------------------------
// Output projection: d_out = g_att[4096,1024] @ Wo[1024,1024]
// ---------------------------------------------------------------------------
__global__ __launch_bounds__(256) void out_gemm_kernel(
    const float* __restrict__ Wo, float* __restrict__ out)
{
    __shared__ float As[16][68];
    __shared__ float Bs[16][68];
    const int m0 = blockIdx.y * 64;
    const int n0 = blockIdx.x * 64;
    const int t  = threadIdx.x;
    const int tx = t & 15, ty = t >> 4;
    const int ar = t >> 2, ak = (t & 3) * 4;
    const int bk = t >> 4, bn = (t & 15) * 4;

    float acc[4][4] = {};

    for (int k0 = 0; k0 < DDIM; k0 += 16) {
        float4 av = *(const float4*)&g_att[(size_t)(m0 + ar) * DDIM + k0 + ak];
        float4 bv = *(const float4*)&Wo[(k0 + bk) * DDIM + n0 + bn];
        __syncthreads();
        As[ak+0][ar] = av.x; As[ak+1][ar] = av.y;
        As[ak+2][ar] = av.z; As[ak+3][ar] = av.w;
        *(float4*)&Bs[bk][bn] = bv;
        __syncthreads();
        #pragma unroll
        for (int kk = 0; kk < 16; kk++) {
            float4 a = *(const float4*)&As[kk][ty*4];
            float4 b = *(const float4*)&Bs[kk][tx*4];
            float aa[4] = {a.x, a.y, a.z, a.w};
            float bb[4] = {b.x, b.y, b.z, b.w};
            #pragma unroll
            for (int i = 0; i < 4; i++)
                #pragma unroll
                for (int j = 0; j < 4; j++)
                    acc[i][j] += aa[i] * bb[j];
        }
    }

    #pragma unroll
    for (int i = 0; i < 4; i++) {
        int mrow = m0 + ty*4 + i;
        float4 r = make_float4(acc[i][0], acc[i][1], acc[i][2], acc[i][3]);
        *(float4*)&out[(size_t)mrow * DDIM + n0 + tx*4] = r;
    }
}

// ---------------------------------------------------------------------------
extern "C" void kernel_launch(void* const* d_in, const int* in_sizes, int n_in,
                              void* d_out, int out_size)
{
    const float* X     = (const float*)d_in[0];
    const float* freqs = (const float*)d_in[1];
    const float* Wq    = (const float*)d_in[2];
    const float* Wk    = (const float*)d_in[3];
    const float* Wv    = (const float*)d_in[4];
    const float* Wo    = (const float*)d_in[5];
    float* out = (float*)d_out;

    cudaFuncSetAttribute(attn_kernel,
                         cudaFuncAttributeMaxDynamicSharedMemorySize, ATT_SMEM);

    qkv_gemm_kernel<<<dim3(16, 64, 3), 256>>>(X, Wq, Wk, Wv, freqs);
    attn_kernel<<<dim3(32, HH, BB), 256, ATT_SMEM>>>();
    out_gemm_kernel<<<dim3(16, 64, 1), 256>>>(Wo, out);
}